// round 4
// baseline (speedup 1.0000x reference)
#include <cuda_runtime.h>
#include <cuda_fp16.h>
#include <mma.h>
#include <math.h>
#include <cstdint>

using namespace nvcuda;

// ================= scratch =================
__device__ __align__(256) float  g_hidden[200000 * 128];
__device__ __align__(256) __half g_embh[1024 * 256];
__device__ __align__(256) float  g_v[1024 * 128];
__device__ __align__(256) float  g_c[1024];

__device__ __forceinline__ float sigf(float x) { return 1.f / (1.f + expf(-x)); }

// ================= hidden precompute: wmma fp16 (unchanged from R3) =================
#define A_LD 72
#define B_LD 136
#define E_LD 68
#define H_SMEM_BYTES (128 * A_LD * 2 + 64 * B_LD * 2)

__global__ __launch_bounds__(256) void hidden_wmma(
    const float* __restrict__ rel, const float* __restrict__ W2a,
    const float* __restrict__ b2a, float* __restrict__ hidden)
{
    extern __shared__ char smem[];
    __half* As = (__half*)smem;
    __half* Bs = (__half*)(smem + 128 * A_LD * 2);
    float*  Es = (float*)smem;

    const int tid = threadIdx.x;
    const int wid = tid >> 5;
    const int m0 = blockIdx.x * 128;

#pragma unroll
    for (int e = tid; e < 128 * 32; e += 256) {
        int row = e >> 5, c2 = (e & 31) << 1;
        int gr = m0 + row; if (gr > 199999) gr = 199999;
        float2 v = *(const float2*)(rel + (size_t)gr * 64 + c2);
        As[row * A_LD + c2]     = __float2half_rn(v.x);
        As[row * A_LD + c2 + 1] = __float2half_rn(v.y);
    }
#pragma unroll
    for (int e = tid; e < 64 * 64; e += 256) {
        int k = e >> 6, c2 = (e & 63) << 1;
        float2 v = *(const float2*)(W2a + (size_t)k * 128 + c2);
        Bs[k * B_LD + c2]     = __float2half_rn(v.x);
        Bs[k * B_LD + c2 + 1] = __float2half_rn(v.y);
    }
    __syncthreads();

    wmma::fragment<wmma::accumulator, 16, 16, 16, float> acc[8];
#pragma unroll
    for (int j = 0; j < 8; ++j) wmma::fill_fragment(acc[j], 0.0f);
#pragma unroll
    for (int k = 0; k < 4; ++k) {
        wmma::fragment<wmma::matrix_a, 16, 16, 16, __half, wmma::row_major> a;
        wmma::load_matrix_sync(a, As + wid * 16 * A_LD + k * 16, A_LD);
#pragma unroll
        for (int j = 0; j < 8; ++j) {
            wmma::fragment<wmma::matrix_b, 16, 16, 16, __half, wmma::row_major> b;
            wmma::load_matrix_sync(b, Bs + k * 16 * B_LD + j * 16, B_LD);
            wmma::mma_sync(acc[j], a, b, acc[j]);
        }
    }

#pragma unroll
    for (int p = 0; p < 2; ++p) {
        __syncthreads();
#pragma unroll
        for (int jj = 0; jj < 4; ++jj)
            wmma::store_matrix_sync(Es + wid * 16 * E_LD + jj * 16, acc[p * 4 + jj],
                                    E_LD, wmma::mem_row_major);
        __syncthreads();
#pragma unroll
        for (int e = tid; e < 128 * 16; e += 256) {
            int row = e >> 4, c4 = (e & 15) << 2;
            int gr = m0 + row;
            if (gr < 200000) {
                int gc = p * 64 + c4;
                float4 o;
                o.x = fmaxf(Es[row * E_LD + c4]     + b2a[gc],     0.f);
                o.y = fmaxf(Es[row * E_LD + c4 + 1] + b2a[gc + 1], 0.f);
                o.z = fmaxf(Es[row * E_LD + c4 + 2] + b2a[gc + 2], 0.f);
                o.w = fmaxf(Es[row * E_LD + c4 + 3] + b2a[gc + 3], 0.f);
                *(float4*)(hidden + (size_t)gr * 128 + gc) = o;
            }
        }
    }
}

// ================= K2: gather + MLP1 (t1, emb) fused, wmma =================
// Block: 64 rows, 256 thr (8 warps: wr=wid>>1 -> 16-row strip, wc=wid&1 -> 128-col half)
// smem: A1h[64][144] | t1h[64][264] | Bh[16][264] | Ef(f32)[64][264]
#define K2_A1H 0
#define K2_T1H (64 * 144 * 2)
#define K2_BH  (K2_T1H + 64 * 264 * 2)
#define K2_EF  (K2_BH + 16 * 264 * 2)
#define K2_SMEM (K2_EF + 64 * 264 * 4)   // 128256

__global__ __launch_bounds__(256) void mlp1_fused(
    const float* __restrict__ node_emb, const int* __restrict__ a0,
    const int* __restrict__ a1, const float* __restrict__ states2,
    const float* __restrict__ W1a, const float* __restrict__ b1a,
    const float* __restrict__ W1b, const float* __restrict__ b1b,
    __half* __restrict__ embh)
{
    extern __shared__ char sm[];
    __half* A1h = (__half*)(sm + K2_A1H);
    __half* t1h = (__half*)(sm + K2_T1H);
    __half* Bh  = (__half*)(sm + K2_BH);
    float*  Ef  = (float*)(sm + K2_EF);

    const int tid = threadIdx.x;
    const int wid = tid >> 5;
    const int wr = wid >> 1, wc = wid & 1;
    const int m0 = blockIdx.x * 64;

    // gather A: [node0 | node1 | t/200 | zeros] -> fp16 [64][144]
    for (int e = tid; e < 64 * 144; e += 256) {
        int r = e / 144, c = e - r * 144;
        int gr = m0 + r;
        float v;
        if (c < 64)        v = node_emb[(size_t)a0[gr] * 64 + c];
        else if (c < 128)  v = node_emb[(size_t)a1[gr] * 64 + (c - 64)];
        else if (c == 128) v = states2[gr] * (1.0f / 200.0f);
        else               v = 0.f;
        A1h[r * 144 + c] = __float2half_rn(v);
    }
    __syncthreads();

    wmma::fragment<wmma::accumulator, 16, 16, 16, float> acc[8];
    wmma::fragment<wmma::matrix_a, 16, 16, 16, __half, wmma::row_major> af;
    wmma::fragment<wmma::matrix_b, 16, 16, 16, __half, wmma::row_major> bf;

    // ---- stage 1: t1 = relu(A @ W1a + b1a), K=129 (9 chunks) ----
#pragma unroll
    for (int j = 0; j < 8; ++j) wmma::fill_fragment(acc[j], 0.0f);
    for (int kc = 0; kc < 9; ++kc) {
        for (int e = tid; e < 16 * 256; e += 256) {
            int r = e >> 8, c = e & 255;
            int gk = kc * 16 + r;
            Bh[r * 264 + c] = (gk < 129) ? __float2half_rn(W1a[(size_t)gk * 256 + c]) : __half(0);
        }
        __syncthreads();
        wmma::load_matrix_sync(af, A1h + wr * 16 * 144 + kc * 16, 144);
#pragma unroll
        for (int j = 0; j < 8; ++j) {
            wmma::load_matrix_sync(bf, Bh + wc * 128 + j * 16, 264);
            wmma::mma_sync(acc[j], af, bf, acc[j]);
        }
        __syncthreads();
    }
#pragma unroll
    for (int j = 0; j < 8; ++j)
        wmma::store_matrix_sync(Ef + (wr * 16) * 264 + wc * 128 + j * 16, acc[j], 264, wmma::mem_row_major);
    __syncthreads();
    for (int e = tid; e < 64 * 256; e += 256) {
        int r = e >> 8, c = e & 255;
        t1h[r * 264 + c] = __float2half_rn(fmaxf(Ef[r * 264 + c] + b1a[c], 0.f));
    }
    __syncthreads();

    // ---- stage 2: emb = t1 @ W1b + b1b, K=256 (16 chunks) ----
#pragma unroll
    for (int j = 0; j < 8; ++j) wmma::fill_fragment(acc[j], 0.0f);
    for (int kc = 0; kc < 16; ++kc) {
        for (int e = tid; e < 16 * 256; e += 256) {
            int r = e >> 8, c = e & 255;
            Bh[r * 264 + c] = __float2half_rn(W1b[(size_t)(kc * 16 + r) * 256 + c]);
        }
        __syncthreads();
        wmma::load_matrix_sync(af, t1h + wr * 16 * 264 + kc * 16, 264);
#pragma unroll
        for (int j = 0; j < 8; ++j) {
            wmma::load_matrix_sync(bf, Bh + wc * 128 + j * 16, 264);
            wmma::mma_sync(acc[j], af, bf, acc[j]);
        }
        __syncthreads();
    }
#pragma unroll
    for (int j = 0; j < 8; ++j)
        wmma::store_matrix_sync(Ef + (wr * 16) * 264 + wc * 128 + j * 16, acc[j], 264, wmma::mem_row_major);
    __syncthreads();
    for (int e = tid; e < 64 * 256; e += 256) {
        int r = e >> 8, c = e & 255;
        embh[(size_t)(m0 + r) * 256 + c] = __float2half_rn(Ef[r * 264 + c] + b1b[c]);
    }
}

// ================= K3: gates GEMM + LSTM fused =================
// grid (16, 4): 64 rows x 64 h-cols; packed gate cols p = g*64+j <-> global g*256+hb+j
// smem: A0h[64][264] (h0 fp16) | Bh[16][264] | Ef[64][264]
#define K3_A0H 0
#define K3_BH  (64 * 264 * 2)
#define K3_EF  (K3_BH + 16 * 264 * 2)
#define K3_SMEM (K3_EF + 64 * 264 * 4)   // 109824

__global__ __launch_bounds__(256) void gates_lstm(
    const __half* __restrict__ embh, const float* __restrict__ h0,
    const float* __restrict__ c0,
    const float* __restrict__ W_ih, const float* __restrict__ W_hh,
    const float* __restrict__ b_ih, const float* __restrict__ b_hh,
    float* __restrict__ out)
{
    extern __shared__ char sm[];
    __half* A0h = (__half*)(sm + K3_A0H);
    __half* Bh  = (__half*)(sm + K3_BH);
    float*  Ef  = (float*)(sm + K3_EF);

    const int tid = threadIdx.x;
    const int wid = tid >> 5;
    const int wr = wid >> 1, wc = wid & 1;
    const int m0 = blockIdx.x * 64;
    const int hb = blockIdx.y * 64;

    for (int e = tid; e < 64 * 256; e += 256) {
        int r = e >> 8, c = e & 255;
        A0h[r * 264 + c] = __float2half_rn(h0[(size_t)(m0 + r) * 256 + c]);
    }
    __syncthreads();

    wmma::fragment<wmma::accumulator, 16, 16, 16, float> acc[8];
#pragma unroll
    for (int j = 0; j < 8; ++j) wmma::fill_fragment(acc[j], 0.0f);
    wmma::fragment<wmma::matrix_a, 16, 16, 16, __half, wmma::row_major> af;
    wmma::fragment<wmma::matrix_b, 16, 16, 16, __half, wmma::row_major> bf;

    for (int ki = 0; ki < 32; ++ki) {
        const float* W = (ki < 16) ? W_ih : W_hh;
        int kr0 = (ki & 15) * 16;
        for (int e = tid; e < 16 * 256; e += 256) {
            int r = e >> 8, p = e & 255;
            int g = p >> 6, j = p & 63;
            Bh[r * 264 + p] = __float2half_rn(W[(size_t)(kr0 + r) * 1024 + g * 256 + hb + j]);
        }
        __syncthreads();
        if (ki < 16)
            wmma::load_matrix_sync(af, embh + (size_t)(m0 + wr * 16) * 256 + ki * 16, 256);
        else
            wmma::load_matrix_sync(af, A0h + wr * 16 * 264 + (ki - 16) * 16, 264);
#pragma unroll
        for (int j = 0; j < 8; ++j) {
            wmma::load_matrix_sync(bf, Bh + wc * 128 + j * 16, 264);
            wmma::mma_sync(acc[j], af, bf, acc[j]);
        }
        __syncthreads();
    }
#pragma unroll
    for (int j = 0; j < 8; ++j)
        wmma::store_matrix_sync(Ef + (wr * 16) * 264 + wc * 128 + j * 16, acc[j], 264, wmma::mem_row_major);
    __syncthreads();

    for (int e = tid; e < 64 * 64; e += 256) {
        int r = e >> 6, j = e & 63;
        float gi = Ef[r * 264 +       j] + b_ih[      hb + j] + b_hh[      hb + j];
        float gf = Ef[r * 264 +  64 + j] + b_ih[256 + hb + j] + b_hh[256 + hb + j];
        float gg = Ef[r * 264 + 128 + j] + b_ih[512 + hb + j] + b_hh[512 + hb + j];
        float go = Ef[r * 264 + 192 + j] + b_ih[768 + hb + j] + b_hh[768 + hb + j];
        int idx = (m0 + r) * 256 + hb + j;
        float c  = c0[idx];
        float cn = sigf(gf) * c + sigf(gi) * tanhf(gg);
        float hn = sigf(go) * tanhf(cn);
        out[524288 + idx]          = hn;
        out[524288 + 262144 + idx] = cn;
    }
}

// ================= K4: t3 + aemb + v + c fused =================
// grid 16 x 64 rows. warps: wr=wid>>1 (16 rows), wc=wid&1.
// smem: A0h[64][264] | t3h[64][144] | aembh[64][72] | W2bh[128][72] | Bh[16][136] | Ef[64][136]
#define K4_A0H  0
#define K4_T3H  (64 * 264 * 2)
#define K4_AEH  (K4_T3H + 64 * 144 * 2)
#define K4_W2B  (K4_AEH + 64 * 72 * 2)
#define K4_BH   (K4_W2B + 128 * 72 * 2)
#define K4_EF   (K4_BH + 16 * 136 * 2)
#define K4_SMEM (K4_EF + 64 * 136 * 4)   // 119040

__global__ __launch_bounds__(256) void tail_fused(
    const float* __restrict__ h1,
    const float* __restrict__ W3a, const float* __restrict__ b3a,
    const float* __restrict__ W3b, const float* __restrict__ b3b,
    const float* __restrict__ W2b, const float* __restrict__ b2b,
    float* __restrict__ v, float* __restrict__ cs)
{
    extern __shared__ char sm[];
    __half* A0h   = (__half*)(sm + K4_A0H);
    __half* t3h   = (__half*)(sm + K4_T3H);
    __half* aembh = (__half*)(sm + K4_AEH);
    __half* W2bh  = (__half*)(sm + K4_W2B);
    __half* Bh    = (__half*)(sm + K4_BH);
    float*  Ef    = (float*)(sm + K4_EF);

    const int tid = threadIdx.x;
    const int wid = tid >> 5;
    const int wr = wid >> 1, wc = wid & 1;
    const int m0 = blockIdx.x * 64;

    for (int e = tid; e < 64 * 256; e += 256) {
        int r = e >> 8, c = e & 255;
        A0h[r * 264 + c] = __float2half_rn(h1[(size_t)(m0 + r) * 256 + c]);
    }
    for (int e = tid; e < 128 * 64; e += 256) {
        int t = e >> 6, n = e & 63;
        W2bh[t * 72 + n] = __float2half_rn(W2b[(size_t)t * 64 + n]);
    }
    __syncthreads();

    wmma::fragment<wmma::matrix_a, 16, 16, 16, __half, wmma::row_major> af;
    wmma::fragment<wmma::matrix_b, 16, 16, 16, __half, wmma::row_major> bf;

    // ---- stage A: t3 = relu(h1 @ W3a + b3a)  [64,128], K=256 ----
    {
        wmma::fragment<wmma::accumulator, 16, 16, 16, float> acc[4];
#pragma unroll
        for (int j = 0; j < 4; ++j) wmma::fill_fragment(acc[j], 0.0f);
        for (int kc = 0; kc < 16; ++kc) {
            for (int e = tid; e < 16 * 128; e += 256) {
                int r = e >> 7, c = e & 127;
                Bh[r * 136 + c] = __float2half_rn(W3a[(size_t)(kc * 16 + r) * 128 + c]);
            }
            __syncthreads();
            wmma::load_matrix_sync(af, A0h + wr * 16 * 264 + kc * 16, 264);
#pragma unroll
            for (int j = 0; j < 4; ++j) {
                wmma::load_matrix_sync(bf, Bh + wc * 64 + j * 16, 136);
                wmma::mma_sync(acc[j], af, bf, acc[j]);
            }
            __syncthreads();
        }
#pragma unroll
        for (int j = 0; j < 4; ++j)
            wmma::store_matrix_sync(Ef + (wr * 16) * 136 + wc * 64 + j * 16, acc[j], 136, wmma::mem_row_major);
        __syncthreads();
        for (int e = tid; e < 64 * 128; e += 256) {
            int r = e >> 7, c = e & 127;
            t3h[r * 144 + c] = __float2half_rn(fmaxf(Ef[r * 136 + c] + b3a[c], 0.f));
        }
        __syncthreads();
    }

    // ---- stage B: aemb = t3 @ W3b + b3b  [64,64], K=128 ----
    {
        wmma::fragment<wmma::accumulator, 16, 16, 16, float> acc[2];
#pragma unroll
        for (int j = 0; j < 2; ++j) wmma::fill_fragment(acc[j], 0.0f);
        for (int kc = 0; kc < 8; ++kc) {
            for (int e = tid; e < 16 * 64; e += 256) {
                int r = e >> 6, c = e & 63;
                Bh[r * 72 + c] = __float2half_rn(W3b[(size_t)(kc * 16 + r) * 64 + c]);
            }
            __syncthreads();
            wmma::load_matrix_sync(af, t3h + wr * 16 * 144 + kc * 16, 144);
#pragma unroll
            for (int j = 0; j < 2; ++j) {
                wmma::load_matrix_sync(bf, Bh + wc * 32 + j * 16, 72);
                wmma::mma_sync(acc[j], af, bf, acc[j]);
            }
            __syncthreads();
        }
#pragma unroll
        for (int j = 0; j < 2; ++j)
            wmma::store_matrix_sync(Ef + (wr * 16) * 72 + wc * 32 + j * 16, acc[j], 72, wmma::mem_row_major);
        __syncthreads();
        for (int e = tid; e < 64 * 64; e += 256) {
            int r = e >> 6, c = e & 63;
            aembh[r * 72 + c] = __float2half_rn(Ef[r * 72 + c] + b3b[c]);
        }
        __syncthreads();
    }

    // ---- stage C: v = aemb @ W2b^T  [64,128], K=64 ; c = aemb . b2b ----
    {
        wmma::fragment<wmma::accumulator, 16, 16, 16, float> acc[4];
#pragma unroll
        for (int j = 0; j < 4; ++j) wmma::fill_fragment(acc[j], 0.0f);
#pragma unroll
        for (int kc = 0; kc < 4; ++kc) {
            wmma::load_matrix_sync(af, aembh + wr * 16 * 72 + kc * 16, 72);
#pragma unroll
            for (int j = 0; j < 4; ++j) {
                wmma::fragment<wmma::matrix_b, 16, 16, 16, __half, wmma::col_major> bc;
                wmma::load_matrix_sync(bc, W2bh + (wc * 64 + j * 16) * 72 + kc * 16, 72);
                wmma::mma_sync(acc[j], af, bc, acc[j]);
            }
        }
        __syncthreads();
#pragma unroll
        for (int j = 0; j < 4; ++j)
            wmma::store_matrix_sync(Ef + (wr * 16) * 136 + wc * 64 + j * 16, acc[j], 136, wmma::mem_row_major);
        __syncthreads();
        for (int e = tid; e < 64 * 128; e += 256) {
            int r = e >> 7, c = e & 127;
            v[(size_t)(m0 + r) * 128 + c] = Ef[r * 136 + c];
        }
        if (tid < 64) {
            float c = 0.f;
#pragma unroll
            for (int n = 0; n < 64; ++n) c += __half2float(aembh[tid * 72 + n]) * b2b[n];
            cs[m0 + tid] = c;
        }
    }
}

// ================= scoring =================
__global__ __launch_bounds__(256) void score_kernel(
    const int* __restrict__ cand, const float* __restrict__ hidden,
    const float* __restrict__ v, const float* __restrict__ cs,
    float* __restrict__ out)
{
    int b = blockIdx.x;
    int l = threadIdx.x & 7;
    int grp = threadIdx.x >> 3;

    float vr[16];
#pragma unroll
    for (int j4 = 0; j4 < 4; ++j4) {
        float4 t = *(const float4*)(v + b * 128 + j4 * 32 + l * 4);
        vr[j4 * 4 + 0] = t.x; vr[j4 * 4 + 1] = t.y;
        vr[j4 * 4 + 2] = t.z; vr[j4 * 4 + 3] = t.w;
    }
    float cb = cs[b];

    for (int k = grp; k < 512; k += 32) {
        int idx = cand[b * 512 + k];
        const float4* row = (const float4*)(hidden + (size_t)idx * 128);
        float acc = 0.f;
#pragma unroll
        for (int j4 = 0; j4 < 4; ++j4) {
            float4 hv = row[j4 * 8 + l];
            acc += hv.x * vr[j4 * 4 + 0] + hv.y * vr[j4 * 4 + 1]
                 + hv.z * vr[j4 * 4 + 2] + hv.w * vr[j4 * 4 + 3];
        }
        acc += __shfl_down_sync(0xffffffffu, acc, 4);
        acc += __shfl_down_sync(0xffffffffu, acc, 2);
        acc += __shfl_down_sync(0xffffffffu, acc, 1);
        if (l == 0) out[b * 512 + k] = (acc + cb) * 0.125f;
    }
}

// ================= launch =================
extern "C" void kernel_launch(void* const* d_in, const int* in_sizes, int n_in,
                              void* d_out, int out_size)
{
    const float* states2  = (const float*)d_in[0];
    const float* h0       = (const float*)d_in[1];
    const float* c0       = (const float*)d_in[2];
    const int*   actions0 = (const int*)d_in[3];
    const int*   actions1 = (const int*)d_in[4];
    const int*   cand     = (const int*)d_in[5];
    const float* node_emb = (const float*)d_in[6];
    const float* rel_emb  = (const float*)d_in[7];
    const float* W1a = (const float*)d_in[8];
    const float* b1a = (const float*)d_in[9];
    const float* W1b = (const float*)d_in[10];
    const float* b1b = (const float*)d_in[11];
    const float* W2a = (const float*)d_in[12];
    const float* b2a = (const float*)d_in[13];
    const float* W2b = (const float*)d_in[14];
    const float* b2b = (const float*)d_in[15];
    const float* W3a = (const float*)d_in[16];
    const float* b3a = (const float*)d_in[17];
    const float* W3b = (const float*)d_in[18];
    const float* b3b = (const float*)d_in[19];
    const float* W_ih = (const float*)d_in[20];
    const float* W_hh = (const float*)d_in[21];
    const float* b_ih = (const float*)d_in[22];
    const float* b_hh = (const float*)d_in[23];
    float* out = (float*)d_out;

    float *p_hidden, *p_v, *p_c;
    __half* p_embh;
    cudaGetSymbolAddress((void**)&p_hidden, g_hidden);
    cudaGetSymbolAddress((void**)&p_embh,   g_embh);
    cudaGetSymbolAddress((void**)&p_v,      g_v);
    cudaGetSymbolAddress((void**)&p_c,      g_c);

    cudaFuncSetAttribute(mlp1_fused, cudaFuncAttributeMaxDynamicSharedMemorySize, K2_SMEM);
    cudaFuncSetAttribute(gates_lstm, cudaFuncAttributeMaxDynamicSharedMemorySize, K3_SMEM);
    cudaFuncSetAttribute(tail_fused, cudaFuncAttributeMaxDynamicSharedMemorySize, K4_SMEM);

    // 1) hidden_all = relu(rel_emb @ W2a + b2a)  [200000 x 128]
    hidden_wmma<<<1563, 256, H_SMEM_BYTES>>>(rel_emb, W2a, b2a, p_hidden);
    // 2) gather + MLP1 -> emb (fp16)
    mlp1_fused<<<16, 256, K2_SMEM>>>(node_emb, actions0, actions1, states2,
                                     W1a, b1a, W1b, b1b, p_embh);
    // 3) gates GEMM + LSTM -> h1, c1 (into out)
    gates_lstm<<<dim3(16, 4), 256, K3_SMEM>>>(p_embh, h0, c0, W_ih, W_hh, b_ih, b_hh, out);
    // 4) t3 + aemb + v + c
    tail_fused<<<16, 256, K4_SMEM>>>(out + 524288, W3a, b3a, W3b, b3b, W2b, b2b, p_v, p_c);
    // 5) values
    score_kernel<<<1024, 256>>>(cand, p_hidden, p_v, p_c, out);
}

// round 5
// speedup vs baseline: 1.7349x; 1.7349x over previous
#include <cuda_runtime.h>
#include <cuda_fp16.h>
#include <mma.h>
#include <math.h>
#include <cstdint>

using namespace nvcuda;

// ================= scratch =================
__device__ __align__(256) __half g_hiddenh[200000 * 128];   // fp16 hidden table (51.2 MB)
__device__ __align__(256) float  g_pre[1024 * 132];
__device__ __align__(256) float  g_t1[1024 * 256];
__device__ __align__(256) float  g_emb[1024 * 256];
__device__ __align__(256) float  g_gates[1024 * 1024];
__device__ __align__(256) float  g_t3[1024 * 128];
__device__ __align__(256) float  g_aemb[1024 * 64];
__device__ __align__(256) float  g_v[1024 * 128];
__device__ __align__(256) float  g_c[1024];

// ================= hidden precompute: wmma fp16, fp16 output =================
#define A_LD 72
#define B_LD 136
#define E_LD 68
#define H_SMEM_BYTES (128 * A_LD * 2 + 64 * B_LD * 2)

__global__ __launch_bounds__(256) void hidden_wmma(
    const float* __restrict__ rel, const float* __restrict__ W2a,
    const float* __restrict__ b2a, __half* __restrict__ hidden)
{
    extern __shared__ char smem[];
    __half* As = (__half*)smem;
    __half* Bs = (__half*)(smem + 128 * A_LD * 2);
    float*  Es = (float*)smem;

    const int tid = threadIdx.x;
    const int wid = tid >> 5;
    const int m0 = blockIdx.x * 128;

#pragma unroll
    for (int e = tid; e < 128 * 32; e += 256) {
        int row = e >> 5, c2 = (e & 31) << 1;
        int gr = m0 + row; if (gr > 199999) gr = 199999;
        float2 v = *(const float2*)(rel + (size_t)gr * 64 + c2);
        As[row * A_LD + c2]     = __float2half_rn(v.x);
        As[row * A_LD + c2 + 1] = __float2half_rn(v.y);
    }
#pragma unroll
    for (int e = tid; e < 64 * 64; e += 256) {
        int k = e >> 6, c2 = (e & 63) << 1;
        float2 v = *(const float2*)(W2a + (size_t)k * 128 + c2);
        Bs[k * B_LD + c2]     = __float2half_rn(v.x);
        Bs[k * B_LD + c2 + 1] = __float2half_rn(v.y);
    }
    __syncthreads();

    wmma::fragment<wmma::accumulator, 16, 16, 16, float> acc[8];
#pragma unroll
    for (int j = 0; j < 8; ++j) wmma::fill_fragment(acc[j], 0.0f);
#pragma unroll
    for (int k = 0; k < 4; ++k) {
        wmma::fragment<wmma::matrix_a, 16, 16, 16, __half, wmma::row_major> a;
        wmma::load_matrix_sync(a, As + wid * 16 * A_LD + k * 16, A_LD);
#pragma unroll
        for (int j = 0; j < 8; ++j) {
            wmma::fragment<wmma::matrix_b, 16, 16, 16, __half, wmma::row_major> b;
            wmma::load_matrix_sync(b, Bs + k * 16 * B_LD + j * 16, B_LD);
            wmma::mma_sync(acc[j], a, b, acc[j]);
        }
    }

#pragma unroll
    for (int p = 0; p < 2; ++p) {
        __syncthreads();
#pragma unroll
        for (int jj = 0; jj < 4; ++jj)
            wmma::store_matrix_sync(Es + wid * 16 * E_LD + jj * 16, acc[p * 4 + jj],
                                    E_LD, wmma::mem_row_major);
        __syncthreads();
#pragma unroll
        for (int e = tid; e < 128 * 16; e += 256) {
            int row = e >> 4, c4 = (e & 15) << 2;
            int gr = m0 + row;
            if (gr < 200000) {
                int gc = p * 64 + c4;
                float ox = fmaxf(Es[row * E_LD + c4]     + b2a[gc],     0.f);
                float oy = fmaxf(Es[row * E_LD + c4 + 1] + b2a[gc + 1], 0.f);
                float oz = fmaxf(Es[row * E_LD + c4 + 2] + b2a[gc + 2], 0.f);
                float ow = fmaxf(Es[row * E_LD + c4 + 3] + b2a[gc + 3], 0.f);
                __half2 p0 = __floats2half2_rn(ox, oy);
                __half2 p1 = __floats2half2_rn(oz, ow);
                __half2* dst = (__half2*)(hidden + (size_t)gr * 128 + gc);
                dst[0] = p0; dst[1] = p1;
            }
        }
    }
}

// ================= full-K small-batch GEMM: tile 32x64, K<=256, ONE sync =================
// smem: As[k][m] 256x36 floats, Bs[k][n] 256x68 floats  (106496 B)
#define FK_AS_LD 36
#define FK_BS_LD 68
#define FK_SMEM (256 * FK_AS_LD * 4 + 256 * FK_BS_LD * 4)

__global__ __launch_bounds__(256) void gemm_fullk(
    const float* __restrict__ A, int lda, int K, const float* __restrict__ B,
    const float* __restrict__ A2, int lda2, int K2, const float* __restrict__ B2,
    const float* __restrict__ bias, const float* __restrict__ bias2,
    float* __restrict__ C, int M, int N, int relu)
{
    extern __shared__ char sm[];
    float* As = (float*)sm;                          // [256][36]
    float* Bs = (float*)(sm + 256 * FK_AS_LD * 4);   // [256][68]

    const int tid = threadIdx.x;
    const int tn = tid & 15, tm = tid >> 4;
    const int m0 = blockIdx.x * 32, n0 = blockIdx.y * 64;

    float acc[2][4];
#pragma unroll
    for (int i = 0; i < 2; i++)
#pragma unroll
        for (int j = 0; j < 4; j++) acc[i][j] = 0.f;

    const int npass = (A2 != nullptr) ? 2 : 1;
    for (int pass = 0; pass < npass; ++pass) {
        const float* Ap = (pass == 0) ? A : A2;
        const float* Bp = (pass == 0) ? B : B2;
        const int Kc    = (pass == 0) ? K : K2;
        const int ldc   = (pass == 0) ? lda : lda2;

        if (pass) __syncthreads();  // protect smem reuse between passes

        // ---- stage ALL of A and B into smem (no intermediate syncs) ----
        for (int k0 = 0; k0 < Kc; k0 += 32) {
            { // A chunk: 32 rows x 32 k
                int r = tid >> 3, c4 = (tid & 7) << 2;
                int gk = k0 + c4, gr = m0 + r;
                float4 v = make_float4(0.f, 0.f, 0.f, 0.f);
                if (gr < M) {
                    if (gk + 3 < Kc) v = *(const float4*)(Ap + (size_t)gr * ldc + gk);
                    else {
                        if (gk     < Kc) v.x = Ap[(size_t)gr * ldc + gk    ];
                        if (gk + 1 < Kc) v.y = Ap[(size_t)gr * ldc + gk + 1];
                        if (gk + 2 < Kc) v.z = Ap[(size_t)gr * ldc + gk + 2];
                        if (gk + 3 < Kc) v.w = Ap[(size_t)gr * ldc + gk + 3];
                    }
                }
                As[(k0 + c4) * FK_AS_LD + r]     = v.x;
                As[(k0 + c4 + 1) * FK_AS_LD + r] = v.y;
                As[(k0 + c4 + 2) * FK_AS_LD + r] = v.z;
                As[(k0 + c4 + 3) * FK_AS_LD + r] = v.w;
            }
#pragma unroll
            for (int it = 0; it < 2; ++it) { // B chunk: 32 k x 64 n
                int f = tid + it * 256;
                int r = f >> 4, c4 = (f & 15) << 2;
                int gk = k0 + r, gn = n0 + c4;
                float4 v = make_float4(0.f, 0.f, 0.f, 0.f);
                if (gk < Kc && gn < N) v = *(const float4*)(Bp + (size_t)gk * N + gn);
                *(float4*)&Bs[(k0 + r) * FK_BS_LD + c4] = v;
            }
        }
        __syncthreads();

        // ---- uninterrupted K loop ----
#pragma unroll 4
        for (int kk = 0; kk < Kc; ++kk) {
            float2 a = *(const float2*)&As[kk * FK_AS_LD + tm * 2];
            float4 b = *(const float4*)&Bs[kk * FK_BS_LD + tn * 4];
            acc[0][0] += a.x * b.x; acc[0][1] += a.x * b.y; acc[0][2] += a.x * b.z; acc[0][3] += a.x * b.w;
            acc[1][0] += a.y * b.x; acc[1][1] += a.y * b.y; acc[1][2] += a.y * b.z; acc[1][3] += a.y * b.w;
        }
    }

#pragma unroll
    for (int i = 0; i < 2; i++) {
        int gm = m0 + tm * 2 + i;
        if (gm >= M) continue;
#pragma unroll
        for (int j = 0; j < 4; j++) {
            int gn = n0 + tn * 4 + j;
            if (gn >= N) continue;
            float x = acc[i][j];
            if (bias)  x += bias[gn];
            if (bias2) x += bias2[gn];
            if (relu)  x = fmaxf(x, 0.f);
            C[(size_t)gm * N + gn] = x;
        }
    }
}

// ================= gather MLP1 input =================
__global__ void gather_pre(const float* __restrict__ node_emb,
                           const int* __restrict__ a0, const int* __restrict__ a1,
                           const float* __restrict__ states2, float* __restrict__ pre)
{
    int b = blockIdx.x;
    int t = threadIdx.x;  // 132
    float v;
    if (t < 64)        v = node_emb[(size_t)a0[b] * 64 + t];
    else if (t < 128)  v = node_emb[(size_t)a1[b] * 64 + (t - 64)];
    else if (t == 128) v = states2[b] * (1.0f / 200.0f);
    else               v = 0.f;
    pre[b * 132 + t] = v;
}

// ================= LSTM cell elementwise =================
__global__ void lstm_kernel(const float* __restrict__ gates, const float* __restrict__ c0,
                            float* __restrict__ out)
{
    int idx = blockIdx.x * blockDim.x + threadIdx.x;
    if (idx >= 1024 * 256) return;
    int b = idx >> 8;
    int h = idx & 255;
    const float* g = gates + (size_t)b * 1024;
    float gi = g[h], gf = g[256 + h], gg = g[512 + h], go = g[768 + h];
    float c = c0[idx];
    float si = 1.f / (1.f + expf(-gi));
    float sf = 1.f / (1.f + expf(-gf));
    float so = 1.f / (1.f + expf(-go));
    float cn = sf * c + si * tanhf(gg);
    float hn = so * tanhf(cn);
    out[524288 + idx]          = hn;
    out[524288 + 262144 + idx] = cn;
}

// ================= v_b = W2b @ a_b ; c_b = a_b . b2b =================
__global__ void compute_v(const float* __restrict__ aemb, const float* __restrict__ W2b,
                          const float* __restrict__ b2b, float* __restrict__ v,
                          float* __restrict__ cs)
{
    __shared__ float a[64];
    int b = blockIdx.x;
    int t = threadIdx.x;  // 128
    if (t < 64) a[t] = aemb[b * 64 + t];
    __syncthreads();
    float acc = 0.f;
#pragma unroll
    for (int n4 = 0; n4 < 16; ++n4) {
        float4 w = *(const float4*)(W2b + t * 64 + n4 * 4);
        acc += w.x * a[n4 * 4] + w.y * a[n4 * 4 + 1] + w.z * a[n4 * 4 + 2] + w.w * a[n4 * 4 + 3];
    }
    v[b * 128 + t] = acc;
    if (t == 0) {
        float c = 0.f;
#pragma unroll
        for (int n = 0; n < 64; ++n) c += a[n] * b2b[n];
        cs[b] = c;
    }
}

// ================= scoring (fp16 hidden rows, 256B each) =================
// 8-lane groups: lane l covers halves [l*8, l*8+8) and [64+l*8, 64+l*8+8)
__global__ __launch_bounds__(256) void score_kernel(
    const int* __restrict__ cand, const __half* __restrict__ hidden,
    const float* __restrict__ v, const float* __restrict__ cs,
    float* __restrict__ out)
{
    int b = blockIdx.x;
    int l = threadIdx.x & 7;
    int grp = threadIdx.x >> 3;

    float vr[16];
#pragma unroll
    for (int j = 0; j < 8; ++j) vr[j]     = v[b * 128 + l * 8 + j];
#pragma unroll
    for (int j = 0; j < 8; ++j) vr[8 + j] = v[b * 128 + 64 + l * 8 + j];
    float cb = cs[b];

    for (int k = grp; k < 512; k += 32) {
        int idx = cand[b * 512 + k];
        const uint4* row = (const uint4*)(hidden + (size_t)idx * 128);
        uint4 q0 = row[l];        // halves l*8..l*8+7
        uint4 q1 = row[8 + l];    // halves 64+l*8..+7
        float acc = 0.f;
        {
            float2 f;
            f = __half22float2(*(__half2*)&q0.x); acc += f.x * vr[0] + f.y * vr[1];
            f = __half22float2(*(__half2*)&q0.y); acc += f.x * vr[2] + f.y * vr[3];
            f = __half22float2(*(__half2*)&q0.z); acc += f.x * vr[4] + f.y * vr[5];
            f = __half22float2(*(__half2*)&q0.w); acc += f.x * vr[6] + f.y * vr[7];
            f = __half22float2(*(__half2*)&q1.x); acc += f.x * vr[8] + f.y * vr[9];
            f = __half22float2(*(__half2*)&q1.y); acc += f.x * vr[10] + f.y * vr[11];
            f = __half22float2(*(__half2*)&q1.z); acc += f.x * vr[12] + f.y * vr[13];
            f = __half22float2(*(__half2*)&q1.w); acc += f.x * vr[14] + f.y * vr[15];
        }
        acc += __shfl_down_sync(0xffffffffu, acc, 4);
        acc += __shfl_down_sync(0xffffffffu, acc, 2);
        acc += __shfl_down_sync(0xffffffffu, acc, 1);
        if (l == 0) out[b * 512 + k] = (acc + cb) * 0.125f;
    }
}

// ================= launch =================
extern "C" void kernel_launch(void* const* d_in, const int* in_sizes, int n_in,
                              void* d_out, int out_size)
{
    const float* states2  = (const float*)d_in[0];
    const float* h0       = (const float*)d_in[1];
    const float* c0       = (const float*)d_in[2];
    const int*   actions0 = (const int*)d_in[3];
    const int*   actions1 = (const int*)d_in[4];
    const int*   cand     = (const int*)d_in[5];
    const float* node_emb = (const float*)d_in[6];
    const float* rel_emb  = (const float*)d_in[7];
    const float* W1a = (const float*)d_in[8];
    const float* b1a = (const float*)d_in[9];
    const float* W1b = (const float*)d_in[10];
    const float* b1b = (const float*)d_in[11];
    const float* W2a = (const float*)d_in[12];
    const float* b2a = (const float*)d_in[13];
    const float* W2b = (const float*)d_in[14];
    const float* b2b = (const float*)d_in[15];
    const float* W3a = (const float*)d_in[16];
    const float* b3a = (const float*)d_in[17];
    const float* W3b = (const float*)d_in[18];
    const float* b3b = (const float*)d_in[19];
    const float* W_ih = (const float*)d_in[20];
    const float* W_hh = (const float*)d_in[21];
    const float* b_ih = (const float*)d_in[22];
    const float* b_hh = (const float*)d_in[23];
    float* out = (float*)d_out;

    __half* p_hiddenh;
    float *p_pre, *p_t1, *p_emb, *p_gates, *p_t3, *p_aemb, *p_v, *p_c;
    cudaGetSymbolAddress((void**)&p_hiddenh, g_hiddenh);
    cudaGetSymbolAddress((void**)&p_pre,    g_pre);
    cudaGetSymbolAddress((void**)&p_t1,     g_t1);
    cudaGetSymbolAddress((void**)&p_emb,    g_emb);
    cudaGetSymbolAddress((void**)&p_gates,  g_gates);
    cudaGetSymbolAddress((void**)&p_t3,     g_t3);
    cudaGetSymbolAddress((void**)&p_aemb,   g_aemb);
    cudaGetSymbolAddress((void**)&p_v,      g_v);
    cudaGetSymbolAddress((void**)&p_c,      g_c);

    cudaFuncSetAttribute(gemm_fullk, cudaFuncAttributeMaxDynamicSharedMemorySize, FK_SMEM);

    // 1) hidden_all (fp16) = relu(rel_emb @ W2a + b2a)  [200000 x 128]
    hidden_wmma<<<1563, 256, H_SMEM_BYTES>>>(rel_emb, W2a, b2a, p_hiddenh);
    // 2) gather pre
    gather_pre<<<1024, 132>>>(node_emb, actions0, actions1, states2, p_pre);
    // 3) t1 = relu(pre @ W1a + b1a)
    gemm_fullk<<<dim3(32, 4), 256, FK_SMEM>>>(p_pre, 132, 129, W1a, nullptr, 0, 0, nullptr,
                                              b1a, nullptr, p_t1, 1024, 256, 1);
    // 4) emb = t1 @ W1b + b1b
    gemm_fullk<<<dim3(32, 4), 256, FK_SMEM>>>(p_t1, 256, 256, W1b, nullptr, 0, 0, nullptr,
                                              b1b, nullptr, p_emb, 1024, 256, 0);
    // 5) gates = emb @ W_ih + h0 @ W_hh + b_ih + b_hh
    gemm_fullk<<<dim3(32, 16), 256, FK_SMEM>>>(p_emb, 256, 256, W_ih, h0, 256, 256, W_hh,
                                               b_ih, b_hh, p_gates, 1024, 1024, 0);
    // 6) LSTM elementwise -> h1, c1
    lstm_kernel<<<1024, 256>>>(p_gates, c0, out);
    // 7) t3 = relu(h1 @ W3a + b3a)
    gemm_fullk<<<dim3(32, 2), 256, FK_SMEM>>>(out + 524288, 256, 256, W3a, nullptr, 0, 0, nullptr,
                                              b3a, nullptr, p_t3, 1024, 128, 1);
    // 8) aemb = t3 @ W3b + b3b
    gemm_fullk<<<dim3(32, 1), 256, FK_SMEM>>>(p_t3, 128, 128, W3b, nullptr, 0, 0, nullptr,
                                              b3b, nullptr, p_aemb, 1024, 64, 0);
    // 9) v_b = W2b @ a_b ; c_b = a_b . b2b
    compute_v<<<1024, 128>>>(p_aemb, W2b, b2b, p_v, p_c);
    // 10) values
    score_kernel<<<1024, 256>>>(cand, p_hiddenh, p_v, p_c, out);
}

// round 6
// speedup vs baseline: 2.0693x; 1.1928x over previous
#include <cuda_runtime.h>
#include <cuda_fp16.h>
#include <mma.h>
#include <math.h>
#include <cstdint>

using namespace nvcuda;

// ================= scratch =================
__device__ __align__(256) __half g_hiddenh[200000 * 128];
__device__ __align__(256) float  g_t1[1024 * 256];
__device__ __align__(256) float  g_emb[1024 * 256];
__device__ __align__(256) float  g_gates[1024 * 1024];
__device__ __align__(256) float  g_t3[1024 * 128];
__device__ __align__(256) float  g_aemb[1024 * 64];
__device__ __align__(256) float  g_v[1024 * 128];
__device__ __align__(256) float  g_c[1024];

// ================= hidden precompute: wmma fp16, fp16 output =================
#define A_LD 72
#define B_LD 136
#define E_LD 68
#define H_SMEM_BYTES (128 * A_LD * 2 + 64 * B_LD * 2)

__global__ __launch_bounds__(256) void hidden_wmma(
    const float* __restrict__ rel, const float* __restrict__ W2a,
    const float* __restrict__ b2a, __half* __restrict__ hidden)
{
    extern __shared__ char smem[];
    __half* As = (__half*)smem;
    __half* Bs = (__half*)(smem + 128 * A_LD * 2);
    float*  Es = (float*)smem;

    const int tid = threadIdx.x;
    const int wid = tid >> 5;
    const int m0 = blockIdx.x * 128;

#pragma unroll
    for (int e = tid; e < 128 * 32; e += 256) {
        int row = e >> 5, c2 = (e & 31) << 1;
        int gr = m0 + row; if (gr > 199999) gr = 199999;
        float2 v = *(const float2*)(rel + (size_t)gr * 64 + c2);
        As[row * A_LD + c2]     = __float2half_rn(v.x);
        As[row * A_LD + c2 + 1] = __float2half_rn(v.y);
    }
#pragma unroll
    for (int e = tid; e < 64 * 64; e += 256) {
        int k = e >> 6, c2 = (e & 63) << 1;
        float2 v = *(const float2*)(W2a + (size_t)k * 128 + c2);
        Bs[k * B_LD + c2]     = __float2half_rn(v.x);
        Bs[k * B_LD + c2 + 1] = __float2half_rn(v.y);
    }
    __syncthreads();

    wmma::fragment<wmma::accumulator, 16, 16, 16, float> acc[8];
#pragma unroll
    for (int j = 0; j < 8; ++j) wmma::fill_fragment(acc[j], 0.0f);
#pragma unroll
    for (int k = 0; k < 4; ++k) {
        wmma::fragment<wmma::matrix_a, 16, 16, 16, __half, wmma::row_major> a;
        wmma::load_matrix_sync(a, As + wid * 16 * A_LD + k * 16, A_LD);
#pragma unroll
        for (int j = 0; j < 8; ++j) {
            wmma::fragment<wmma::matrix_b, 16, 16, 16, __half, wmma::row_major> b;
            wmma::load_matrix_sync(b, Bs + k * 16 * B_LD + j * 16, B_LD);
            wmma::mma_sync(acc[j], a, b, acc[j]);
        }
    }

#pragma unroll
    for (int p = 0; p < 2; ++p) {
        __syncthreads();
#pragma unroll
        for (int jj = 0; jj < 4; ++jj)
            wmma::store_matrix_sync(Es + wid * 16 * E_LD + jj * 16, acc[p * 4 + jj],
                                    E_LD, wmma::mem_row_major);
        __syncthreads();
#pragma unroll
        for (int e = tid; e < 128 * 16; e += 256) {
            int row = e >> 4, c4 = (e & 15) << 2;
            int gr = m0 + row;
            if (gr < 200000) {
                int gc = p * 64 + c4;
                float ox = fmaxf(Es[row * E_LD + c4]     + b2a[gc],     0.f);
                float oy = fmaxf(Es[row * E_LD + c4 + 1] + b2a[gc + 1], 0.f);
                float oz = fmaxf(Es[row * E_LD + c4 + 2] + b2a[gc + 2], 0.f);
                float ow = fmaxf(Es[row * E_LD + c4 + 3] + b2a[gc + 3], 0.f);
                __half2 p0 = __floats2half2_rn(ox, oy);
                __half2 p1 = __floats2half2_rn(oz, ow);
                __half2* dst = (__half2*)(hidden + (size_t)gr * 128 + gc);
                dst[0] = p0; dst[1] = p1;
            }
        }
    }
}

// ================= chain GEMM via wmma: tile 32x64, full-K fp16 staging =================
// C[M,N] = act(A@B (+ A2@B2) + bias (+bias2)); optional fused gather for A (first layer).
// smem: Ah[32][264] fp16 (16896B) | Bh[256][72] fp16 (36864B); Ef[32][72] f32 aliases Ah.
#define W_ALD 264
#define W_BLD 72
#define W_ELD 72
#define W_SMEM (32 * W_ALD * 2 + 256 * W_BLD * 2)   // 53760

__global__ __launch_bounds__(256) void gemm_wmma(
    const float* __restrict__ A, int lda, int K, const float* __restrict__ B,
    const float* __restrict__ A2, int lda2, int K2, const float* __restrict__ B2,
    const float* __restrict__ bias, const float* __restrict__ bias2,
    float* __restrict__ C, int M, int N, int relu,
    const float* __restrict__ node_emb, const int* __restrict__ ga0,
    const int* __restrict__ ga1, const float* __restrict__ gst)
{
    extern __shared__ char sm[];
    __half* Ah = (__half*)sm;
    __half* Bh = (__half*)(sm + 32 * W_ALD * 2);
    float*  Ef = (float*)sm;

    const int tid = threadIdx.x;
    const int wid = tid >> 5;
    const int wr = wid & 1;        // m-tile (2 x 16 rows)
    const int wc = wid >> 1;       // n-tile (4 x 16 cols)
    const int m0 = blockIdx.x * 32, n0 = blockIdx.y * 64;

    wmma::fragment<wmma::accumulator, 16, 16, 16, float> acc;
    wmma::fill_fragment(acc, 0.0f);
    wmma::fragment<wmma::matrix_a, 16, 16, 16, __half, wmma::row_major> af;
    wmma::fragment<wmma::matrix_b, 16, 16, 16, __half, wmma::row_major> bf;

    const int npass = (A2 != nullptr) ? 2 : 1;
    for (int pass = 0; pass < npass; ++pass) {
        const float* Ap = (pass == 0) ? A : A2;
        const float* Bp = (pass == 0) ? B : B2;
        const int Kc    = (pass == 0) ? K : K2;
        const int ldc   = (pass == 0) ? lda : lda2;
        const int KPAD  = (Kc + 15) & ~15;

        if (pass) __syncthreads();

        // ---- stage A (32 x KPAD) ----
        if (pass == 0 && node_emb != nullptr) {
            // gather mode: [node0 | node1 | t/200 | zeros], Kc=129
            for (int e = tid; e < 32 * 144; e += 256) {
                int r = e / 144, c = e - r * 144;
                int gr = m0 + r;
                float v;
                if (c < 64)        v = node_emb[(size_t)ga0[gr] * 64 + c];
                else if (c < 128)  v = node_emb[(size_t)ga1[gr] * 64 + (c - 64)];
                else if (c == 128) v = gst[gr] * (1.0f / 200.0f);
                else               v = 0.f;
                Ah[r * W_ALD + c] = __float2half_rn(v);
            }
        } else {
            int half_e = KPAD >> 1;
            for (int e = tid; e < 32 * half_e; e += 256) {
                int r = e / half_e, c2 = (e - r * half_e) << 1;
                int gr = m0 + r;
                __half2 h = __half2half2(__half(0));
                if (gr < M && c2 < Kc) {
                    if (c2 + 1 < Kc) {
                        float2 v = *(const float2*)(Ap + (size_t)gr * ldc + c2);
                        h = __floats2half2_rn(v.x, v.y);
                    } else {
                        h = __floats2half2_rn(Ap[(size_t)gr * ldc + c2], 0.f);
                    }
                }
                *(__half2*)&Ah[r * W_ALD + c2] = h;
            }
        }
        // ---- stage B (KPAD x 64) ----
        for (int e = tid; e < KPAD * 16; e += 256) {
            int r = e >> 4, c4 = (e & 15) << 2;
            int gn = n0 + c4;
            __half2 h0v = __half2half2(__half(0)), h1v = h0v;
            if (r < Kc && gn < N) {
                float4 v = *(const float4*)(Bp + (size_t)r * N + gn);
                h0v = __floats2half2_rn(v.x, v.y);
                h1v = __floats2half2_rn(v.z, v.w);
            }
            *(__half2*)&Bh[r * W_BLD + c4]     = h0v;
            *(__half2*)&Bh[r * W_BLD + c4 + 2] = h1v;
        }
        __syncthreads();

        // ---- MMA: KPAD/16 steps ----
        const int nk = KPAD >> 4;
        for (int kc = 0; kc < nk; ++kc) {
            wmma::load_matrix_sync(af, Ah + wr * 16 * W_ALD + kc * 16, W_ALD);
            wmma::load_matrix_sync(bf, Bh + (kc * 16) * W_BLD + wc * 16, W_BLD);
            wmma::mma_sync(acc, af, bf, acc);
        }
    }

    // ---- epilogue ----
    __syncthreads();   // Ah fully consumed before aliasing as Ef
    wmma::store_matrix_sync(Ef + (wr * 16) * W_ELD + wc * 16, acc, W_ELD, wmma::mem_row_major);
    __syncthreads();
    for (int e = tid; e < 32 * 16; e += 256) {
        int r = e >> 4, c4 = (e & 15) << 2;
        int gm = m0 + r;
        if (gm >= M) continue;
        int gn = n0 + c4;
        if (gn >= N) continue;
        float4 x = *(const float4*)&Ef[r * W_ELD + c4];
        if (bias)  { x.x += bias[gn]; x.y += bias[gn+1]; x.z += bias[gn+2]; x.w += bias[gn+3]; }
        if (bias2) { x.x += bias2[gn]; x.y += bias2[gn+1]; x.z += bias2[gn+2]; x.w += bias2[gn+3]; }
        if (relu) {
            x.x = fmaxf(x.x, 0.f); x.y = fmaxf(x.y, 0.f);
            x.z = fmaxf(x.z, 0.f); x.w = fmaxf(x.w, 0.f);
        }
        *(float4*)(C + (size_t)gm * N + gn) = x;
    }
}

// ================= LSTM cell elementwise =================
__global__ void lstm_kernel(const float* __restrict__ gates, const float* __restrict__ c0,
                            float* __restrict__ out)
{
    int idx = blockIdx.x * blockDim.x + threadIdx.x;
    if (idx >= 1024 * 256) return;
    int b = idx >> 8;
    int h = idx & 255;
    const float* g = gates + (size_t)b * 1024;
    float gi = g[h], gf = g[256 + h], gg = g[512 + h], go = g[768 + h];
    float c = c0[idx];
    float si = 1.f / (1.f + expf(-gi));
    float sf = 1.f / (1.f + expf(-gf));
    float so = 1.f / (1.f + expf(-go));
    float cn = sf * c + si * tanhf(gg);
    float hn = so * tanhf(cn);
    out[524288 + idx]          = hn;
    out[524288 + 262144 + idx] = cn;
}

// ================= v_b = W2b @ a_b ; c_b = a_b . b2b =================
__global__ void compute_v(const float* __restrict__ aemb, const float* __restrict__ W2b,
                          const float* __restrict__ b2b, float* __restrict__ v,
                          float* __restrict__ cs)
{
    __shared__ float a[64];
    int b = blockIdx.x;
    int t = threadIdx.x;  // 128
    if (t < 64) a[t] = aemb[b * 64 + t];
    __syncthreads();
    float acc = 0.f;
#pragma unroll
    for (int n4 = 0; n4 < 16; ++n4) {
        float4 w = *(const float4*)(W2b + t * 64 + n4 * 4);
        acc += w.x * a[n4 * 4] + w.y * a[n4 * 4 + 1] + w.z * a[n4 * 4 + 2] + w.w * a[n4 * 4 + 3];
    }
    v[b * 128 + t] = acc;
    if (t == 0) {
        float c = 0.f;
#pragma unroll
        for (int n = 0; n < 64; ++n) c += a[n] * b2b[n];
        cs[b] = c;
    }
}

// ================= scoring (fp16 hidden rows, 256B each) =================
__global__ __launch_bounds__(256) void score_kernel(
    const int* __restrict__ cand, const __half* __restrict__ hidden,
    const float* __restrict__ v, const float* __restrict__ cs,
    float* __restrict__ out)
{
    int b = blockIdx.x;
    int l = threadIdx.x & 7;
    int grp = threadIdx.x >> 3;

    float vr[16];
#pragma unroll
    for (int j = 0; j < 8; ++j) vr[j]     = v[b * 128 + l * 8 + j];
#pragma unroll
    for (int j = 0; j < 8; ++j) vr[8 + j] = v[b * 128 + 64 + l * 8 + j];
    float cb = cs[b];

    for (int k = grp; k < 512; k += 32) {
        int idx = cand[b * 512 + k];
        const uint4* row = (const uint4*)(hidden + (size_t)idx * 128);
        uint4 q0 = row[l];
        uint4 q1 = row[8 + l];
        float acc = 0.f;
        {
            float2 f;
            f = __half22float2(*(__half2*)&q0.x); acc += f.x * vr[0] + f.y * vr[1];
            f = __half22float2(*(__half2*)&q0.y); acc += f.x * vr[2] + f.y * vr[3];
            f = __half22float2(*(__half2*)&q0.z); acc += f.x * vr[4] + f.y * vr[5];
            f = __half22float2(*(__half2*)&q0.w); acc += f.x * vr[6] + f.y * vr[7];
            f = __half22float2(*(__half2*)&q1.x); acc += f.x * vr[8] + f.y * vr[9];
            f = __half22float2(*(__half2*)&q1.y); acc += f.x * vr[10] + f.y * vr[11];
            f = __half22float2(*(__half2*)&q1.z); acc += f.x * vr[12] + f.y * vr[13];
            f = __half22float2(*(__half2*)&q1.w); acc += f.x * vr[14] + f.y * vr[15];
        }
        acc += __shfl_down_sync(0xffffffffu, acc, 4);
        acc += __shfl_down_sync(0xffffffffu, acc, 2);
        acc += __shfl_down_sync(0xffffffffu, acc, 1);
        if (l == 0) out[b * 512 + k] = (acc + cb) * 0.125f;
    }
}

// ================= launch =================
extern "C" void kernel_launch(void* const* d_in, const int* in_sizes, int n_in,
                              void* d_out, int out_size)
{
    const float* states2  = (const float*)d_in[0];
    const float* h0       = (const float*)d_in[1];
    const float* c0       = (const float*)d_in[2];
    const int*   actions0 = (const int*)d_in[3];
    const int*   actions1 = (const int*)d_in[4];
    const int*   cand     = (const int*)d_in[5];
    const float* node_emb = (const float*)d_in[6];
    const float* rel_emb  = (const float*)d_in[7];
    const float* W1a = (const float*)d_in[8];
    const float* b1a = (const float*)d_in[9];
    const float* W1b = (const float*)d_in[10];
    const float* b1b = (const float*)d_in[11];
    const float* W2a = (const float*)d_in[12];
    const float* b2a = (const float*)d_in[13];
    const float* W2b = (const float*)d_in[14];
    const float* b2b = (const float*)d_in[15];
    const float* W3a = (const float*)d_in[16];
    const float* b3a = (const float*)d_in[17];
    const float* W3b = (const float*)d_in[18];
    const float* b3b = (const float*)d_in[19];
    const float* W_ih = (const float*)d_in[20];
    const float* W_hh = (const float*)d_in[21];
    const float* b_ih = (const float*)d_in[22];
    const float* b_hh = (const float*)d_in[23];
    float* out = (float*)d_out;

    __half* p_hiddenh;
    float *p_t1, *p_emb, *p_gates, *p_t3, *p_aemb, *p_v, *p_c;
    cudaGetSymbolAddress((void**)&p_hiddenh, g_hiddenh);
    cudaGetSymbolAddress((void**)&p_t1,     g_t1);
    cudaGetSymbolAddress((void**)&p_emb,    g_emb);
    cudaGetSymbolAddress((void**)&p_gates,  g_gates);
    cudaGetSymbolAddress((void**)&p_t3,     g_t3);
    cudaGetSymbolAddress((void**)&p_aemb,   g_aemb);
    cudaGetSymbolAddress((void**)&p_v,      g_v);
    cudaGetSymbolAddress((void**)&p_c,      g_c);

    cudaFuncSetAttribute(gemm_wmma, cudaFuncAttributeMaxDynamicSharedMemorySize, W_SMEM);

    // 1) hidden_all (fp16) = relu(rel_emb @ W2a + b2a)  [200000 x 128]
    hidden_wmma<<<1563, 256, H_SMEM_BYTES>>>(rel_emb, W2a, b2a, p_hiddenh);
    // 2) t1 = relu(gather(pre) @ W1a + b1a)   (gather fused)
    gemm_wmma<<<dim3(32, 4), 256, W_SMEM>>>(nullptr, 0, 129, W1a, nullptr, 0, 0, nullptr,
                                            b1a, nullptr, p_t1, 1024, 256, 1,
                                            node_emb, actions0, actions1, states2);
    // 3) emb = t1 @ W1b + b1b
    gemm_wmma<<<dim3(32, 4), 256, W_SMEM>>>(p_t1, 256, 256, W1b, nullptr, 0, 0, nullptr,
                                            b1b, nullptr, p_emb, 1024, 256, 0,
                                            nullptr, nullptr, nullptr, nullptr);
    // 4) gates = emb @ W_ih + h0 @ W_hh + b_ih + b_hh
    gemm_wmma<<<dim3(32, 16), 256, W_SMEM>>>(p_emb, 256, 256, W_ih, h0, 256, 256, W_hh,
                                             b_ih, b_hh, p_gates, 1024, 1024, 0,
                                             nullptr, nullptr, nullptr, nullptr);
    // 5) LSTM elementwise -> h1, c1
    lstm_kernel<<<1024, 256>>>(p_gates, c0, out);
    // 6) t3 = relu(h1 @ W3a + b3a)
    gemm_wmma<<<dim3(32, 2), 256, W_SMEM>>>(out + 524288, 256, 256, W3a, nullptr, 0, 0, nullptr,
                                            b3a, nullptr, p_t3, 1024, 128, 1,
                                            nullptr, nullptr, nullptr, nullptr);
    // 7) aemb = t3 @ W3b + b3b
    gemm_wmma<<<dim3(32, 1), 256, W_SMEM>>>(p_t3, 128, 128, W3b, nullptr, 0, 0, nullptr,
                                            b3b, nullptr, p_aemb, 1024, 64, 0,
                                            nullptr, nullptr, nullptr, nullptr);
    // 8) v_b = W2b @ a_b ; c_b = a_b . b2b
    compute_v<<<1024, 128>>>(p_aemb, W2b, b2b, p_v, p_c);
    // 9) values
    score_kernel<<<1024, 256>>>(cand, p_hiddenh, p_v, p_c, out);
}